// round 16
// baseline (speedup 1.0000x reference)
#include <cuda_runtime.h>
#include <cuda_bf16.h>
#include <cstdint>
#include <cstddef>

#define NB  2
#define NH  12
#define HD  64
#define SEQ 2048
#define EMB 768
#define NCOL 2304  // 3*NH*HD
#define MROWS (NB * SEQ)   // 4096

// bf16 split operands produced by the QKV GEMM epilogue.
// Q, K: [bh][n][d] (row-major per head). V: transposed [bh][d][n].
__device__ __nv_bfloat16 g_Qh[NB * NH * SEQ * HD];
__device__ __nv_bfloat16 g_Ql[NB * NH * SEQ * HD];
__device__ __nv_bfloat16 g_Kh[NB * NH * SEQ * HD];
__device__ __nv_bfloat16 g_Kl[NB * NH * SEQ * HD];
__device__ __nv_bfloat16 g_VTh[NB * NH * HD * SEQ];
__device__ __nv_bfloat16 g_VTl[NB * NH * HD * SEQ];
// bf16 split operands for the QKV MMA inputs.
__device__ __nv_bfloat16 g_zh[MROWS * EMB];
__device__ __nv_bfloat16 g_zl[MROWS * EMB];
__device__ __nv_bfloat16 g_WhT[NCOL * EMB];   // [n][k] = W[k][n] hi
__device__ __nv_bfloat16 g_WlT[NCOL * EMB];   // lo

static __device__ __forceinline__ uint32_t smem_u32(const void* p) {
    uint32_t a;
    asm("{ .reg .u64 t; cvta.to.shared.u64 t, %1; cvt.u32.u64 %0, t; }"
        : "=r"(a) : "l"(p));
    return a;
}

// ---------------- HMMA / async-copy helpers (plain sm_103 target) ---------
#define LDM_X4(r, a) \
    asm volatile("ldmatrix.sync.aligned.m8n8.x4.shared.b16 {%0,%1,%2,%3}, [%4];" \
        : "=r"((r)[0]), "=r"((r)[1]), "=r"((r)[2]), "=r"((r)[3]) : "r"(a))
#define LDM_X2(r, a) \
    asm volatile("ldmatrix.sync.aligned.m8n8.x2.shared.b16 {%0,%1}, [%2];" \
        : "=r"((r)[0]), "=r"((r)[1]) : "r"(a))
#define MMA_BF16(d, a, b) \
    asm volatile("mma.sync.aligned.m16n8k16.row.col.f32.bf16.bf16.f32 " \
        "{%0,%1,%2,%3}, {%4,%5,%6,%7}, {%8,%9}, {%0,%1,%2,%3};" \
        : "+f"((d)[0]), "+f"((d)[1]), "+f"((d)[2]), "+f"((d)[3]) \
        : "r"((a)[0]), "r"((a)[1]), "r"((a)[2]), "r"((a)[3]), \
          "r"((b)[0]), "r"((b)[1]))

static __device__ __forceinline__ void cp16(uint32_t s, const void* g) {
    asm volatile("cp.async.cg.shared.global [%0], [%1], 16;" :: "r"(s), "l"(g));
}
#define CP_COMMIT()  asm volatile("cp.async.commit_group;" ::: "memory")
#define CP_WAIT(n)   asm volatile("cp.async.wait_group %0;" :: "n"(n) : "memory")

static __device__ __forceinline__ uint32_t cvt_bf16x2(float hi, float lo) {
    uint32_t r;
    asm("cvt.rn.bf16x2.f32 %0, %1, %2;" : "=r"(r) : "f"(hi), "f"(lo));
    return r;
}

// ============================================================================
// Kernel A+B fused: z split  |  W transpose + split  (one launch).
// Blocks [0, ZB): z quads. Blocks [ZB, ZB+WB): W 32x32 tiles.
// ============================================================================
#define ZB ((MROWS * EMB / 4) / 256)   // 3072
#define WB ((NCOL / 32) * (EMB / 32))  // 72*24 = 1728

__global__ void convert_fused_kernel(const float* __restrict__ z,
                                     const float* __restrict__ W)
{
    if (blockIdx.x < ZB) {
        int i4 = blockIdx.x * 256 + threadIdx.x;
        float4 v = ((const float4*)z)[i4];
        __nv_bfloat16 h0 = __float2bfloat16(v.x);
        __nv_bfloat16 h1 = __float2bfloat16(v.y);
        __nv_bfloat16 h2 = __float2bfloat16(v.z);
        __nv_bfloat16 h3 = __float2bfloat16(v.w);
        __nv_bfloat162* zh2 = (__nv_bfloat162*)g_zh;
        __nv_bfloat162* zl2 = (__nv_bfloat162*)g_zl;
        zh2[i4 * 2]     = __nv_bfloat162(h0, h1);
        zh2[i4 * 2 + 1] = __nv_bfloat162(h2, h3);
        zl2[i4 * 2]     = __nv_bfloat162(__float2bfloat16(v.x - __bfloat162float(h0)),
                                         __float2bfloat16(v.y - __bfloat162float(h1)));
        zl2[i4 * 2 + 1] = __nv_bfloat162(__float2bfloat16(v.z - __bfloat162float(h2)),
                                         __float2bfloat16(v.w - __bfloat162float(h3)));
    } else {
        __shared__ float t[32][33];
        int wi = blockIdx.x - ZB;
        const int n0 = (wi % (NCOL / 32)) * 32;
        const int k0 = (wi / (NCOL / 32)) * 32;
        const int tx = threadIdx.x & 31, ty = threadIdx.x >> 5;   // 32 x 8
#pragma unroll
        for (int i = 0; i < 4; i++)
            t[ty + 8 * i][tx] = W[(size_t)(k0 + ty + 8 * i) * NCOL + n0 + tx];
        __syncthreads();
#pragma unroll
        for (int i = 0; i < 4; i++) {
            float v = t[tx][ty + 8 * i];
            __nv_bfloat16 h = __float2bfloat16(v);
            size_t o = (size_t)(n0 + ty + 8 * i) * EMB + k0 + tx;
            g_WhT[o] = h;
            g_WlT[o] = __float2bfloat16(v - __bfloat162float(h));
        }
    }
}

// ============================================================================
// Kernel C: QKV GEMM via HMMA, bf16x3 — cp.async double-buffered k32 chunks,
// smem-staged coalesced epilogue (R14 winner, unchanged).
// ============================================================================
#define AP2 40                      // smem pitch in bf16 for k32 chunk
#define QARR_B (128 * AP2 * 2)      // 10240 bytes per array
#define QSTG_B (4 * QARR_B)         // 40960 bytes per stage
#define DP 133                      // fp32 staging pitch

__global__ __launch_bounds__(256, 2)
void qkv_mma_kernel(const float* __restrict__ bias)
{
    extern __shared__ __nv_bfloat16 smb[];
    const uint32_t uS0 = smem_u32(smb);
    const uint32_t uS1 = uS0 + QSTG_B;

    const int tid  = threadIdx.x;
    const int lane = tid & 31;
    const int wid  = tid >> 5;
    const int wm = (wid >> 2) << 6;
    const int wn = (wid & 3) << 5;
    const int m0 = blockIdx.y * 128;
    const int n0 = blockIdx.x * 128;

    float acc[4][4][4];
#pragma unroll
    for (int mt = 0; mt < 4; mt++)
#pragma unroll
        for (int nt = 0; nt < 4; nt++)
#pragma unroll
            for (int e = 0; e < 4; e++) acc[mt][nt][e] = 0.f;

    const uint32_t a_off = (uint32_t)((wm + (lane & 15)) * AP2 + ((lane >> 4) << 3)) * 2;
    const uint32_t b_off = (uint32_t)((wn + (lane & 7)) * AP2 + (((lane >> 3) & 1) << 3)) * 2;

    // ---- prologue: chunk 0 -> stage 0 ----
    {
#pragma unroll
        for (int j = 0; j < 2; j++) {
            int idx = tid + j * 256;
            int r = idx >> 2, c = (idx & 3) * 8;
            uint32_t so = (uint32_t)(r * AP2 + c) * 2;
            size_t ga = (size_t)(m0 + r) * EMB + c;
            size_t gb = (size_t)(n0 + r) * EMB + c;
            cp16(uS0 + so,              &g_zh[ga]);
            cp16(uS0 + QARR_B + so,     &g_zl[ga]);
            cp16(uS0 + 2 * QARR_B + so, &g_WhT[gb]);
            cp16(uS0 + 3 * QARR_B + so, &g_WlT[gb]);
        }
        CP_COMMIT();
    }

    for (int kc = 0; kc < 24; kc++) {
        const uint32_t cur = (kc & 1) ? uS1 : uS0;
        CP_WAIT(0);
        __syncthreads();

        if (kc < 23) {
            const int kb = (kc + 1) * 32;
            const uint32_t nxt = (kc & 1) ? uS0 : uS1;
#pragma unroll
            for (int j = 0; j < 2; j++) {
                int idx = tid + j * 256;
                int r = idx >> 2, c = (idx & 3) * 8;
                uint32_t so = (uint32_t)(r * AP2 + c) * 2;
                size_t ga = (size_t)(m0 + r) * EMB + kb + c;
                size_t gb = (size_t)(n0 + r) * EMB + kb + c;
                cp16(nxt + so,              &g_zh[ga]);
                cp16(nxt + QARR_B + so,     &g_zl[ga]);
                cp16(nxt + 2 * QARR_B + so, &g_WhT[gb]);
                cp16(nxt + 3 * QARR_B + so, &g_WlT[gb]);
            }
            CP_COMMIT();
        }

        const uint32_t uAh = cur, uAl = cur + QARR_B;
        const uint32_t uBh = cur + 2 * QARR_B, uBl = cur + 3 * QARR_B;
#pragma unroll
        for (int ks = 0; ks < 2; ks++) {
            const uint32_t kof = (uint32_t)(ks * 16) * 2;
            uint32_t ah[4][4], al[4][4], bh[4][2], bl[4][2];
#pragma unroll
            for (int mt = 0; mt < 4; mt++) {
                uint32_t ad = a_off + kof + (uint32_t)(mt * 16 * AP2) * 2;
                LDM_X4(ah[mt], uAh + ad);
                LDM_X4(al[mt], uAl + ad);
            }
#pragma unroll
            for (int nt = 0; nt < 4; nt++) {
                uint32_t bd = b_off + kof + (uint32_t)(nt * 8 * AP2) * 2;
                LDM_X2(bh[nt], uBh + bd);
                LDM_X2(bl[nt], uBl + bd);
            }
#pragma unroll
            for (int mt = 0; mt < 4; mt++)
#pragma unroll
                for (int nt = 0; nt < 4; nt++) {
                    MMA_BF16(acc[mt][nt], ah[mt], bh[nt]);
                    MMA_BF16(acc[mt][nt], ah[mt], bl[nt]);
                    MMA_BF16(acc[mt][nt], al[mt], bh[nt]);
                }
        }
    }

    // ---- Epilogue: stage D to smem, then coalesced writeback. ----
    __syncthreads();
    float* Ds = (float*)smb;         // [128][DP] fp32
    {
        const int g_ = lane >> 2;
        const int t2_ = (lane & 3) << 1;
#pragma unroll
        for (int mt = 0; mt < 4; mt++)
#pragma unroll
            for (int e2i = 0; e2i < 2; e2i++) {
                int row = wm + mt * 16 + g_ + e2i * 8;
#pragma unroll
                for (int nt = 0; nt < 4; nt++) {
                    int col = wn + nt * 8 + t2_;
                    Ds[row * DP + col]     = acc[mt][nt][e2i * 2 + 0];
                    Ds[row * DP + col + 1] = acc[mt][nt][e2i * 2 + 1];
                }
            }
    }
    __syncthreads();

    const int n0m3 = n0 % 3;
    for (int p = wid; p < 512; p += 8) {
        int m = p >> 2;
        int sQ = (p >> 1) & 1;
        int half = p & 1;
        int s = sQ ? 2 : 0;
        int cl = ((s + 3 - n0m3) % 3) + 3 * (half * 32 + lane);
        if (cl < 128) {
            int c = n0 + cl;
            int h = c / 192;
            int d = (c - 192 * h) / 3;
            float v = Ds[m * DP + cl] + bias[c];
            __nv_bfloat16 vh = __float2bfloat16(v);
            __nv_bfloat16 vl = __float2bfloat16(v - __bfloat162float(vh));
            int mrow = m0 + m;
            size_t idx = (((size_t)((mrow >> 11) * NH + h)) * SEQ + (mrow & 2047)) * HD + d;
            if (sQ) { g_Qh[idx] = vh; g_Ql[idx] = vl; }
            else    { g_Kh[idx] = vh; g_Kl[idx] = vl; }
        }
    }
    {
        const int cl0v = (1 + 3 - n0m3) % 3;
        for (int q = wid; ; q += 8) {
            int cl = cl0v + 3 * (q >> 1);
            if (cl >= 128) break;
            int mh = (q & 1) << 6;
            int c = n0 + cl;
            int h = c / 192;
            int d = (c - 192 * h) / 3;
            float bc = bias[c];
            int mb = mh + 2 * lane;
            float v0 = Ds[mb * DP + cl] + bc;
            float v1 = Ds[(mb + 1) * DP + cl] + bc;
            __nv_bfloat16 h0 = __float2bfloat16(v0);
            __nv_bfloat16 h1 = __float2bfloat16(v1);
            __nv_bfloat16 l0 = __float2bfloat16(v0 - __bfloat162float(h0));
            __nv_bfloat16 l1 = __float2bfloat16(v1 - __bfloat162float(h1));
            int mrow = m0 + mb;
            size_t idx = (((size_t)((mrow >> 11) * NH + h)) * HD + d) * SEQ + (mrow & 2047);
            *(__nv_bfloat162*)&g_VTh[idx] = __nv_bfloat162(h0, h1);
            *(__nv_bfloat162*)&g_VTl[idx] = __nv_bfloat162(l0, l1);
        }
    }
}

// ============================================================================
// Kernel D: attention via HMMA bf16x3 — R10 pipeline with the V-wait HOISTED
// before exp, so exp -> PV runs barrier-free and ptxas can overlap MUFU exp
// with tensor MMAs (split as exp0-3, PV(bs0), exp4-7, PV(bs1)).
// Smem: 6 x 9216 B = 54 KB -> 3 CTAs/SM. No-max softmax; 0.125 folded into
// the final store (reference bug preserved).
// ============================================================================
#define AT 72
#define ARR_B (64 * AT * 2)   // 9216 bytes per hi/lo array

__global__ __launch_bounds__(128, 3)
void attn_hmma_kernel(float* __restrict__ out)
{
    extern __shared__ __nv_bfloat16 sb[];
    __nv_bfloat16* sQh = sb;
    __nv_bfloat16* sQl = sb + 64 * AT;
    const uint32_t uQh = smem_u32(sQh), uQl = smem_u32(sQl);
    const uint32_t uKh = uQh + 2 * ARR_B, uKl = uQh + 3 * ARR_B;
    const uint32_t uVh = uQh + 4 * ARR_B, uVl = uQh + 5 * ARR_B;

    const int tid = threadIdx.x;
    const int lane = tid & 31;
    const int wq = tid >> 5;
    const int q0 = blockIdx.x << 6;
    const int bh = blockIdx.y;

    const __nv_bfloat16* gQh = g_Qh + (size_t)bh * SEQ * HD;
    const __nv_bfloat16* gQl = g_Ql + (size_t)bh * SEQ * HD;
    const __nv_bfloat16* gKh = g_Kh + (size_t)bh * SEQ * HD;
    const __nv_bfloat16* gKl = g_Kl + (size_t)bh * SEQ * HD;
    const __nv_bfloat16* gVh = g_VTh + (size_t)bh * HD * SEQ;
    const __nv_bfloat16* gVl = g_VTl + (size_t)bh * HD * SEQ;

    // ---- Prologue: K(0) group, V(0) group, Q direct loads. ----
#pragma unroll
    for (int j = 0; j < 4; j++) {
        int idx = tid + j * 128;
        int r = idx >> 3, c = (idx & 7) * 8;
        uint32_t so = (uint32_t)(r * AT + c) * 2;
        size_t gk = (size_t)r * HD + c;
        cp16(uKh + so, &gKh[gk]);
        cp16(uKl + so, &gKl[gk]);
    }
    CP_COMMIT();
#pragma unroll
    for (int j = 0; j < 4; j++) {
        int idx = tid + j * 128;
        int r = idx >> 3, c = (idx & 7) * 8;
        uint32_t so = (uint32_t)(r * AT + c) * 2;
        size_t gv = (size_t)r * SEQ + c;
        cp16(uVh + so, &gVh[gv]);
        cp16(uVl + so, &gVl[gv]);
    }
    CP_COMMIT();
#pragma unroll
    for (int j = 0; j < 4; j++) {
        int idx = tid + j * 128;
        int r = idx >> 3, c = (idx & 7) * 8;
        uint32_t so = (uint32_t)(r * AT + c) * 2;
        size_t go = (size_t)(q0 + r) * HD + c;
        *(uint4*)((char*)sQh + so) = *(const uint4*)&gQh[go];
        *(uint4*)((char*)sQl + so) = *(const uint4*)&gQl[go];
    }
    __syncthreads();

    // Q fragments: loop-invariant, register-resident.
    const uint32_t a_off = (uint32_t)((wq * 16 + (lane & 15)) * AT + ((lane >> 4) << 3)) * 2;
    uint32_t qh[4][4], ql[4][4];
#pragma unroll
    for (int ks = 0; ks < 4; ks++) {
        LDM_X4(qh[ks], uQh + a_off + ks * 32);
        LDM_X4(ql[ks], uQl + a_off + ks * 32);
    }

    const uint32_t b_off = (uint32_t)((lane & 7) * AT + (((lane >> 3) & 3) << 3)) * 2;

    float oacc[8][4];
#pragma unroll
    for (int j = 0; j < 8; j++)
#pragma unroll
        for (int e = 0; e < 4; e++) oacc[j][e] = 0.f;
    float lsum0 = 0.f, lsum1 = 0.f;

    for (int kt = 0; kt < 32; kt++) {
        // ---- wait K(kt); outstanding after it: V(kt) ----
        CP_WAIT(1);
        __syncthreads();

        // ---- S = Q K^T : warp tile 16q x 64k. ----
        float sacc[8][4];
#pragma unroll
        for (int j = 0; j < 8; j++)
#pragma unroll
            for (int e = 0; e < 4; e++) sacc[j][e] = 0.f;

#pragma unroll
        for (int bs = 0; bs < 2; bs++) {
#pragma unroll
            for (int j = 0; j < 8; j++) {
                uint32_t kh4[4], kl4[4];
                uint32_t bd = b_off + (uint32_t)(j * 8 * AT) * 2 + bs * 64;
                LDM_X4(kh4, uKh + bd);
                LDM_X4(kl4, uKl + bd);
                MMA_BF16(sacc[j], qh[2 * bs], (kh4 + 0));
                MMA_BF16(sacc[j], qh[2 * bs], (kl4 + 0));
                MMA_BF16(sacc[j], ql[2 * bs], (kh4 + 0));
                MMA_BF16(sacc[j], qh[2 * bs + 1], (kh4 + 2));
                MMA_BF16(sacc[j], qh[2 * bs + 1], (kl4 + 2));
                MMA_BF16(sacc[j], ql[2 * bs + 1], (kh4 + 2));
            }
        }

        __syncthreads();   // all warps done reading Kbuf
        if (kt < 31) {     // prefetch K(kt+1) into Kbuf
            const int kn = (kt + 1) << 6;
#pragma unroll
            for (int j = 0; j < 4; j++) {
                int idx = tid + j * 128;
                int r = idx >> 3, c = (idx & 7) * 8;
                uint32_t so = (uint32_t)(r * AT + c) * 2;
                size_t gk = (size_t)(kn + r) * HD + c;
                cp16(uKh + so, &gKh[gk]);
                cp16(uKl + so, &gKl[gk]);
            }
            CP_COMMIT();
        }

        // ---- V(kt) resident check BEFORE exp: leaves exp->PV barrier-free
        //      so MUFU exp overlaps tensor MMA issue. V was committed a full
        //      tile ago; this wait is expected to be a no-op.
        if (kt < 31) { CP_WAIT(1); } else { CP_WAIT(0); }
        __syncthreads();

        // ---- exp(j0..3) -> ph/pl[0..1], then PV(bs0); exp(j4..7) -> [2..3],
        //      then PV(bs1). Straight-line: ptxas interleaves MUFU with MMA.
        uint32_t ph[4][4], pl[4][4];
#pragma unroll
        for (int half = 0; half < 2; half++) {
#pragma unroll
            for (int jj = 0; jj < 4; jj++) {
                const int j = half * 4 + jj;
                float e0 = __expf(sacc[j][0]);
                float e1 = __expf(sacc[j][1]);
                float e2 = __expf(sacc[j][2]);
                float e3 = __expf(sacc[j][3]);
                lsum0 += e0 + e1;
                lsum1 += e2 + e3;
                int t = j >> 1, hf = (j & 1) << 1;
                uint32_t p01 = cvt_bf16x2(e1, e0);
                uint32_t p23 = cvt_bf16x2(e3, e2);
                ph[t][hf + 0] = p01;
                ph[t][hf + 1] = p23;
                float r0 = e0 - __uint_as_float(p01 << 16);
                float r1 = e1 - __uint_as_float(p01 & 0xffff0000u);
                float r2 = e2 - __uint_as_float(p23 << 16);
                float r3 = e3 - __uint_as_float(p23 & 0xffff0000u);
                pl[t][hf + 0] = cvt_bf16x2(r1, r0);
                pl[t][hf + 1] = cvt_bf16x2(r3, r2);
            }
            // PV for this k32 half: bs = half.
#pragma unroll
            for (int j = 0; j < 8; j++) {
                uint32_t vh4[4], vl4[4];
                uint32_t bd = b_off + (uint32_t)(j * 8 * AT) * 2 + half * 64;
                LDM_X4(vh4, uVh + bd);
                LDM_X4(vl4, uVl + bd);
                MMA_BF16(oacc[j], ph[2 * half], (vh4 + 0));
                MMA_BF16(oacc[j], ph[2 * half], (vl4 + 0));
                MMA_BF16(oacc[j], pl[2 * half], (vh4 + 0));
                MMA_BF16(oacc[j], ph[2 * half + 1], (vh4 + 2));
                MMA_BF16(oacc[j], ph[2 * half + 1], (vl4 + 2));
                MMA_BF16(oacc[j], pl[2 * half + 1], (vh4 + 2));
            }
        }

        if (kt < 31) {
            __syncthreads();   // all warps done reading Vbuf
            const int kn = (kt + 1) << 6;
#pragma unroll
            for (int j = 0; j < 4; j++) {
                int idx = tid + j * 128;
                int r = idx >> 3, c = (idx & 7) * 8;
                uint32_t so = (uint32_t)(r * AT + c) * 2;
                size_t gv = (size_t)r * SEQ + kn + c;
                cp16(uVh + so, &gVh[gv]);
                cp16(uVl + so, &gVl[gv]);
            }
            CP_COMMIT();
        }
    }

    // ---- Epilogue ----
#pragma unroll
    for (int off = 1; off < 4; off <<= 1) {
        lsum0 += __shfl_xor_sync(0xffffffffu, lsum0, off);
        lsum1 += __shfl_xor_sync(0xffffffffu, lsum1, off);
    }
    const float inv0 = 0.125f / lsum0;
    const float inv1 = 0.125f / lsum1;

    const int g = lane >> 2;
    const int t2 = (lane & 3) << 1;
    const int b = bh / NH;
    const int h = bh - b * NH;
    const int row0 = q0 + wq * 16 + g;
    float* base0 = out + ((size_t)(b * SEQ + row0)) * EMB + h * HD;
    float* base1 = base0 + (size_t)8 * EMB;
#pragma unroll
    for (int j = 0; j < 8; j++) {
        *(float2*)&base0[j * 8 + t2] = make_float2(oacc[j][0] * inv0, oacc[j][1] * inv0);
        *(float2*)&base1[j * 8 + t2] = make_float2(oacc[j][2] * inv1, oacc[j][3] * inv1);
    }
}

// ============================================================================
extern "C" void kernel_launch(void* const* d_in, const int* in_sizes, int n_in,
                              void* d_out, int out_size)
{
    const float* z = nullptr;
    const float* W = nullptr;
    const float* bias = nullptr;
    for (int i = 0; i < n_in; i++) {
        if (in_sizes[i] == NB * SEQ * EMB)      z = (const float*)d_in[i];
        else if (in_sizes[i] == EMB * NCOL)     W = (const float*)d_in[i];
        else if (in_sizes[i] == NCOL)           bias = (const float*)d_in[i];
    }
    float* out = (float*)d_out;

    convert_fused_kernel<<<ZB + WB, 256>>>(z, W);

    const int mma_smem = 2 * QSTG_B;   // 81920
    cudaFuncSetAttribute(qkv_mma_kernel, cudaFuncAttributeMaxDynamicSharedMemorySize,
                         mma_smem);
    qkv_mma_kernel<<<dim3(NCOL / 128, MROWS / 128), 256, mma_smem>>>(bias);

    const int attn_smem = 6 * ARR_B;   // 55296
    cudaFuncSetAttribute(attn_hmma_kernel, cudaFuncAttributeMaxDynamicSharedMemorySize,
                         attn_smem);
    attn_hmma_kernel<<<dim3(SEQ / 64, NB * NH), 128, attn_smem>>>(out);
}

// round 17
// speedup vs baseline: 1.0559x; 1.0559x over previous
#include <cuda_runtime.h>
#include <cuda_bf16.h>
#include <cstdint>
#include <cstddef>

#define NB  2
#define NH  12
#define HD  64
#define SEQ 2048
#define EMB 768
#define NCOL 2304  // 3*NH*HD
#define MROWS (NB * SEQ)   // 4096

// bf16 split operands produced by the QKV GEMM epilogue.
// Q, K: [bh][n][d] (row-major per head). V: transposed [bh][d][n].
__device__ __nv_bfloat16 g_Qh[NB * NH * SEQ * HD];
__device__ __nv_bfloat16 g_Ql[NB * NH * SEQ * HD];
__device__ __nv_bfloat16 g_Kh[NB * NH * SEQ * HD];
__device__ __nv_bfloat16 g_Kl[NB * NH * SEQ * HD];
__device__ __nv_bfloat16 g_VTh[NB * NH * HD * SEQ];
__device__ __nv_bfloat16 g_VTl[NB * NH * HD * SEQ];
// bf16 split operands for the QKV MMA inputs.
__device__ __nv_bfloat16 g_zh[MROWS * EMB];
__device__ __nv_bfloat16 g_zl[MROWS * EMB];
__device__ __nv_bfloat16 g_WhT[NCOL * EMB];   // [n][k] = W[k][n] hi
__device__ __nv_bfloat16 g_WlT[NCOL * EMB];   // lo

static __device__ __forceinline__ uint32_t smem_u32(const void* p) {
    uint32_t a;
    asm("{ .reg .u64 t; cvta.to.shared.u64 t, %1; cvt.u32.u64 %0, t; }"
        : "=r"(a) : "l"(p));
    return a;
}

// ---------------- HMMA / async-copy helpers (plain sm_103 target) ---------
#define LDM_X4(r, a) \
    asm volatile("ldmatrix.sync.aligned.m8n8.x4.shared.b16 {%0,%1,%2,%3}, [%4];" \
        : "=r"((r)[0]), "=r"((r)[1]), "=r"((r)[2]), "=r"((r)[3]) : "r"(a))
#define LDM_X2(r, a) \
    asm volatile("ldmatrix.sync.aligned.m8n8.x2.shared.b16 {%0,%1}, [%2];" \
        : "=r"((r)[0]), "=r"((r)[1]) : "r"(a))
#define MMA_BF16(d, a, b) \
    asm volatile("mma.sync.aligned.m16n8k16.row.col.f32.bf16.bf16.f32 " \
        "{%0,%1,%2,%3}, {%4,%5,%6,%7}, {%8,%9}, {%0,%1,%2,%3};" \
        : "+f"((d)[0]), "+f"((d)[1]), "+f"((d)[2]), "+f"((d)[3]) \
        : "r"((a)[0]), "r"((a)[1]), "r"((a)[2]), "r"((a)[3]), \
          "r"((b)[0]), "r"((b)[1]))

static __device__ __forceinline__ void cp16(uint32_t s, const void* g) {
    asm volatile("cp.async.cg.shared.global [%0], [%1], 16;" :: "r"(s), "l"(g));
}
#define CP_COMMIT()  asm volatile("cp.async.commit_group;" ::: "memory")
#define CP_WAIT(n)   asm volatile("cp.async.wait_group %0;" :: "n"(n) : "memory")

static __device__ __forceinline__ uint32_t cvt_bf16x2(float hi, float lo) {
    uint32_t r;
    asm("cvt.rn.bf16x2.f32 %0, %1, %2;" : "=r"(r) : "f"(hi), "f"(lo));
    return r;
}

// ============================================================================
// Kernel A+B fused: z split  |  W transpose + split  (one launch).
// ============================================================================
#define ZB ((MROWS * EMB / 4) / 256)   // 3072
#define WB ((NCOL / 32) * (EMB / 32))  // 1728

__global__ void convert_fused_kernel(const float* __restrict__ z,
                                     const float* __restrict__ W)
{
    if (blockIdx.x < ZB) {
        int i4 = blockIdx.x * 256 + threadIdx.x;
        float4 v = ((const float4*)z)[i4];
        __nv_bfloat16 h0 = __float2bfloat16(v.x);
        __nv_bfloat16 h1 = __float2bfloat16(v.y);
        __nv_bfloat16 h2 = __float2bfloat16(v.z);
        __nv_bfloat16 h3 = __float2bfloat16(v.w);
        __nv_bfloat162* zh2 = (__nv_bfloat162*)g_zh;
        __nv_bfloat162* zl2 = (__nv_bfloat162*)g_zl;
        zh2[i4 * 2]     = __nv_bfloat162(h0, h1);
        zh2[i4 * 2 + 1] = __nv_bfloat162(h2, h3);
        zl2[i4 * 2]     = __nv_bfloat162(__float2bfloat16(v.x - __bfloat162float(h0)),
                                         __float2bfloat16(v.y - __bfloat162float(h1)));
        zl2[i4 * 2 + 1] = __nv_bfloat162(__float2bfloat16(v.z - __bfloat162float(h2)),
                                         __float2bfloat16(v.w - __bfloat162float(h3)));
    } else {
        __shared__ float t[32][33];
        int wi = blockIdx.x - ZB;
        const int n0 = (wi % (NCOL / 32)) * 32;
        const int k0 = (wi / (NCOL / 32)) * 32;
        const int tx = threadIdx.x & 31, ty = threadIdx.x >> 5;   // 32 x 8
#pragma unroll
        for (int i = 0; i < 4; i++)
            t[ty + 8 * i][tx] = W[(size_t)(k0 + ty + 8 * i) * NCOL + n0 + tx];
        __syncthreads();
#pragma unroll
        for (int i = 0; i < 4; i++) {
            float v = t[tx][ty + 8 * i];
            __nv_bfloat16 h = __float2bfloat16(v);
            size_t o = (size_t)(n0 + ty + 8 * i) * EMB + k0 + tx;
            g_WhT[o] = h;
            g_WlT[o] = __float2bfloat16(v - __bfloat162float(h));
        }
    }
}

// ============================================================================
// Kernel C: QKV GEMM via HMMA, bf16x3 — cp.async double-buffered k32 chunks,
// smem-staged coalesced epilogue. NEW: B fragments via ldmatrix.x4 (two n8
// tiles per instruction), halving B-side LDSM count.
// ============================================================================
#define AP2 40                      // smem pitch in bf16 for k32 chunk
#define QARR_B (128 * AP2 * 2)      // 10240 bytes per array
#define QSTG_B (4 * QARR_B)         // 40960 bytes per stage
#define DP 133                      // fp32 staging pitch

__global__ __launch_bounds__(256, 2)
void qkv_mma_kernel(const float* __restrict__ bias)
{
    extern __shared__ __nv_bfloat16 smb[];
    const uint32_t uS0 = smem_u32(smb);
    const uint32_t uS1 = uS0 + QSTG_B;

    const int tid  = threadIdx.x;
    const int lane = tid & 31;
    const int wid  = tid >> 5;
    const int wm = (wid >> 2) << 6;
    const int wn = (wid & 3) << 5;
    const int m0 = blockIdx.y * 128;
    const int n0 = blockIdx.x * 128;

    float acc[4][4][4];
#pragma unroll
    for (int mt = 0; mt < 4; mt++)
#pragma unroll
        for (int nt = 0; nt < 4; nt++)
#pragma unroll
            for (int e = 0; e < 4; e++) acc[mt][nt][e] = 0.f;

    const uint32_t a_off = (uint32_t)((wm + (lane & 15)) * AP2 + ((lane >> 4) << 3)) * 2;
    // B x4 offset: lanes 0-15 -> n8 tile np*2, lanes 16-31 -> tile np*2+1.
    const uint32_t b_off4 = (uint32_t)((wn + ((lane >> 4) << 3) + (lane & 7)) * AP2
                                       + (((lane >> 3) & 1) << 3)) * 2;

    // ---- prologue: chunk 0 -> stage 0 ----
    {
#pragma unroll
        for (int j = 0; j < 2; j++) {
            int idx = tid + j * 256;
            int r = idx >> 2, c = (idx & 3) * 8;
            uint32_t so = (uint32_t)(r * AP2 + c) * 2;
            size_t ga = (size_t)(m0 + r) * EMB + c;
            size_t gb = (size_t)(n0 + r) * EMB + c;
            cp16(uS0 + so,              &g_zh[ga]);
            cp16(uS0 + QARR_B + so,     &g_zl[ga]);
            cp16(uS0 + 2 * QARR_B + so, &g_WhT[gb]);
            cp16(uS0 + 3 * QARR_B + so, &g_WlT[gb]);
        }
        CP_COMMIT();
    }

    for (int kc = 0; kc < 24; kc++) {
        const uint32_t cur = (kc & 1) ? uS1 : uS0;
        CP_WAIT(0);
        __syncthreads();

        if (kc < 23) {
            const int kb = (kc + 1) * 32;
            const uint32_t nxt = (kc & 1) ? uS0 : uS1;
#pragma unroll
            for (int j = 0; j < 2; j++) {
                int idx = tid + j * 256;
                int r = idx >> 2, c = (idx & 3) * 8;
                uint32_t so = (uint32_t)(r * AP2 + c) * 2;
                size_t ga = (size_t)(m0 + r) * EMB + kb + c;
                size_t gb = (size_t)(n0 + r) * EMB + kb + c;
                cp16(nxt + so,              &g_zh[ga]);
                cp16(nxt + QARR_B + so,     &g_zl[ga]);
                cp16(nxt + 2 * QARR_B + so, &g_WhT[gb]);
                cp16(nxt + 3 * QARR_B + so, &g_WlT[gb]);
            }
            CP_COMMIT();
        }

        const uint32_t uAh = cur, uAl = cur + QARR_B;
        const uint32_t uBh = cur + 2 * QARR_B, uBl = cur + 3 * QARR_B;
#pragma unroll
        for (int ks = 0; ks < 2; ks++) {
            const uint32_t kof = (uint32_t)(ks * 16) * 2;
            uint32_t ah[4][4], al[4][4], bh[2][4], bl[2][4];
#pragma unroll
            for (int mt = 0; mt < 4; mt++) {
                uint32_t ad = a_off + kof + (uint32_t)(mt * 16 * AP2) * 2;
                LDM_X4(ah[mt], uAh + ad);
                LDM_X4(al[mt], uAl + ad);
            }
#pragma unroll
            for (int np = 0; np < 2; np++) {   // n8 tile pair (2 tiles per x4)
                uint32_t bd = b_off4 + kof + (uint32_t)(np * 16 * AP2) * 2;
                LDM_X4(bh[np], uBh + bd);
                LDM_X4(bl[np], uBl + bd);
            }
#pragma unroll
            for (int mt = 0; mt < 4; mt++)
#pragma unroll
                for (int nt = 0; nt < 4; nt++) {
                    const uint32_t* bhf = bh[nt >> 1] + ((nt & 1) << 1);
                    const uint32_t* blf = bl[nt >> 1] + ((nt & 1) << 1);
                    MMA_BF16(acc[mt][nt], ah[mt], bhf);
                    MMA_BF16(acc[mt][nt], ah[mt], blf);
                    MMA_BF16(acc[mt][nt], al[mt], bhf);
                }
        }
    }

    // ---- Epilogue: stage D to smem, then coalesced writeback. ----
    __syncthreads();
    float* Ds = (float*)smb;         // [128][DP] fp32
    {
        const int g_ = lane >> 2;
        const int t2_ = (lane & 3) << 1;
#pragma unroll
        for (int mt = 0; mt < 4; mt++)
#pragma unroll
            for (int e2i = 0; e2i < 2; e2i++) {
                int row = wm + mt * 16 + g_ + e2i * 8;
#pragma unroll
                for (int nt = 0; nt < 4; nt++) {
                    int col = wn + nt * 8 + t2_;
                    Ds[row * DP + col]     = acc[mt][nt][e2i * 2 + 0];
                    Ds[row * DP + col + 1] = acc[mt][nt][e2i * 2 + 1];
                }
            }
    }
    __syncthreads();

    const int n0m3 = n0 % 3;
    for (int p = wid; p < 512; p += 8) {
        int m = p >> 2;
        int sQ = (p >> 1) & 1;
        int half = p & 1;
        int s = sQ ? 2 : 0;
        int cl = ((s + 3 - n0m3) % 3) + 3 * (half * 32 + lane);
        if (cl < 128) {
            int c = n0 + cl;
            int h = c / 192;
            int d = (c - 192 * h) / 3;
            float v = Ds[m * DP + cl] + bias[c];
            __nv_bfloat16 vh = __float2bfloat16(v);
            __nv_bfloat16 vl = __float2bfloat16(v - __bfloat162float(vh));
            int mrow = m0 + m;
            size_t idx = (((size_t)((mrow >> 11) * NH + h)) * SEQ + (mrow & 2047)) * HD + d;
            if (sQ) { g_Qh[idx] = vh; g_Ql[idx] = vl; }
            else    { g_Kh[idx] = vh; g_Kl[idx] = vl; }
        }
    }
    {
        const int cl0v = (1 + 3 - n0m3) % 3;
        for (int q = wid; ; q += 8) {
            int cl = cl0v + 3 * (q >> 1);
            if (cl >= 128) break;
            int mh = (q & 1) << 6;
            int c = n0 + cl;
            int h = c / 192;
            int d = (c - 192 * h) / 3;
            float bc = bias[c];
            int mb = mh + 2 * lane;
            float v0 = Ds[mb * DP + cl] + bc;
            float v1 = Ds[(mb + 1) * DP + cl] + bc;
            __nv_bfloat16 h0 = __float2bfloat16(v0);
            __nv_bfloat16 h1 = __float2bfloat16(v1);
            __nv_bfloat16 l0 = __float2bfloat16(v0 - __bfloat162float(h0));
            __nv_bfloat16 l1 = __float2bfloat16(v1 - __bfloat162float(h1));
            int mrow = m0 + mb;
            size_t idx = (((size_t)((mrow >> 11) * NH + h)) * HD + d) * SEQ + (mrow & 2047);
            *(__nv_bfloat162*)&g_VTh[idx] = __nv_bfloat162(h0, h1);
            *(__nv_bfloat162*)&g_VTl[idx] = __nv_bfloat162(l0, l1);
        }
    }
}

// ============================================================================
// Kernel D: attention via HMMA bf16x3 — EXACT R10/R14 structure (221.5 us
// measured, three times; every schedule perturbation has lost). Phase-
// pipelined single K/V buffers. No-max softmax; 0.125 applied post-softmax
// (reference bug preserved). Smem 54 KB -> 3 CTAs/SM.
// ============================================================================
#define AT 72
#define ARR_B (64 * AT * 2)   // 9216 bytes per hi/lo array

__global__ __launch_bounds__(128, 3)
void attn_hmma_kernel(float* __restrict__ out)
{
    extern __shared__ __nv_bfloat16 sb[];
    __nv_bfloat16* sQh = sb;
    __nv_bfloat16* sQl = sb + 64 * AT;
    const uint32_t uQh = smem_u32(sQh), uQl = smem_u32(sQl);
    const uint32_t uKh = uQh + 2 * ARR_B, uKl = uQh + 3 * ARR_B;
    const uint32_t uVh = uQh + 4 * ARR_B, uVl = uQh + 5 * ARR_B;

    const int tid = threadIdx.x;
    const int lane = tid & 31;
    const int wq = tid >> 5;
    const int q0 = blockIdx.x << 6;
    const int bh = blockIdx.y;

    const __nv_bfloat16* gQh = g_Qh + (size_t)bh * SEQ * HD;
    const __nv_bfloat16* gQl = g_Ql + (size_t)bh * SEQ * HD;
    const __nv_bfloat16* gKh = g_Kh + (size_t)bh * SEQ * HD;
    const __nv_bfloat16* gKl = g_Kl + (size_t)bh * SEQ * HD;
    const __nv_bfloat16* gVh = g_VTh + (size_t)bh * HD * SEQ;
    const __nv_bfloat16* gVl = g_VTl + (size_t)bh * HD * SEQ;

    // ---- Prologue: K(0) group, V(0) group, Q direct loads. ----
#pragma unroll
    for (int j = 0; j < 4; j++) {
        int idx = tid + j * 128;
        int r = idx >> 3, c = (idx & 7) * 8;
        uint32_t so = (uint32_t)(r * AT + c) * 2;
        size_t gk = (size_t)r * HD + c;
        cp16(uKh + so, &gKh[gk]);
        cp16(uKl + so, &gKl[gk]);
    }
    CP_COMMIT();
#pragma unroll
    for (int j = 0; j < 4; j++) {
        int idx = tid + j * 128;
        int r = idx >> 3, c = (idx & 7) * 8;
        uint32_t so = (uint32_t)(r * AT + c) * 2;
        size_t gv = (size_t)r * SEQ + c;
        cp16(uVh + so, &gVh[gv]);
        cp16(uVl + so, &gVl[gv]);
    }
    CP_COMMIT();
#pragma unroll
    for (int j = 0; j < 4; j++) {
        int idx = tid + j * 128;
        int r = idx >> 3, c = (idx & 7) * 8;
        uint32_t so = (uint32_t)(r * AT + c) * 2;
        size_t go = (size_t)(q0 + r) * HD + c;
        *(uint4*)((char*)sQh + so) = *(const uint4*)&gQh[go];
        *(uint4*)((char*)sQl + so) = *(const uint4*)&gQl[go];
    }
    __syncthreads();

    // Q fragments: loop-invariant, register-resident.
    const uint32_t a_off = (uint32_t)((wq * 16 + (lane & 15)) * AT + ((lane >> 4) << 3)) * 2;
    uint32_t qh[4][4], ql[4][4];
#pragma unroll
    for (int ks = 0; ks < 4; ks++) {
        LDM_X4(qh[ks], uQh + a_off + ks * 32);
        LDM_X4(ql[ks], uQl + a_off + ks * 32);
    }

    const uint32_t b_off = (uint32_t)((lane & 7) * AT + (((lane >> 3) & 3) << 3)) * 2;

    float oacc[8][4];
#pragma unroll
    for (int j = 0; j < 8; j++)
#pragma unroll
        for (int e = 0; e < 4; e++) oacc[j][e] = 0.f;
    float lsum0 = 0.f, lsum1 = 0.f;

    for (int kt = 0; kt < 32; kt++) {
        // ---- wait K(kt); outstanding after it: V(kt) ----
        CP_WAIT(1);
        __syncthreads();

        // ---- S = Q K^T : warp tile 16q x 64k. ----
        float sacc[8][4];
#pragma unroll
        for (int j = 0; j < 8; j++)
#pragma unroll
            for (int e = 0; e < 4; e++) sacc[j][e] = 0.f;

#pragma unroll
        for (int bs = 0; bs < 2; bs++) {
#pragma unroll
            for (int j = 0; j < 8; j++) {
                uint32_t kh4[4], kl4[4];
                uint32_t bd = b_off + (uint32_t)(j * 8 * AT) * 2 + bs * 64;
                LDM_X4(kh4, uKh + bd);
                LDM_X4(kl4, uKl + bd);
                MMA_BF16(sacc[j], qh[2 * bs], (kh4 + 0));
                MMA_BF16(sacc[j], qh[2 * bs], (kl4 + 0));
                MMA_BF16(sacc[j], ql[2 * bs], (kh4 + 0));
                MMA_BF16(sacc[j], qh[2 * bs + 1], (kh4 + 2));
                MMA_BF16(sacc[j], qh[2 * bs + 1], (kl4 + 2));
                MMA_BF16(sacc[j], ql[2 * bs + 1], (kh4 + 2));
            }
        }

        __syncthreads();   // all warps done reading Kbuf
        if (kt < 31) {     // prefetch K(kt+1) into Kbuf (overlaps exp + PV)
            const int kn = (kt + 1) << 6;
#pragma unroll
            for (int j = 0; j < 4; j++) {
                int idx = tid + j * 128;
                int r = idx >> 3, c = (idx & 7) * 8;
                uint32_t so = (uint32_t)(r * AT + c) * 2;
                size_t gk = (size_t)(kn + r) * HD + c;
                cp16(uKh + so, &gKh[gk]);
                cp16(uKl + so, &gKl[gk]);
            }
            CP_COMMIT();
        }

        // ---- exp + C-frag -> PV A-frag conversion (registers only). ----
        uint32_t ph[4][4], pl[4][4];
#pragma unroll
        for (int j = 0; j < 8; j++) {
            float e0 = __expf(sacc[j][0]);
            float e1 = __expf(sacc[j][1]);
            float e2 = __expf(sacc[j][2]);
            float e3 = __expf(sacc[j][3]);
            lsum0 += e0 + e1;
            lsum1 += e2 + e3;
            int t = j >> 1, hf = (j & 1) << 1;
            uint32_t p01 = cvt_bf16x2(e1, e0);
            uint32_t p23 = cvt_bf16x2(e3, e2);
            ph[t][hf + 0] = p01;
            ph[t][hf + 1] = p23;
            float r0 = e0 - __uint_as_float(p01 << 16);
            float r1 = e1 - __uint_as_float(p01 & 0xffff0000u);
            float r2 = e2 - __uint_as_float(p23 << 16);
            float r3 = e3 - __uint_as_float(p23 & 0xffff0000u);
            pl[t][hf + 0] = cvt_bf16x2(r1, r0);
            pl[t][hf + 1] = cvt_bf16x2(r3, r2);
        }

        // ---- wait V(kt); outstanding after it: K(kt+1) if issued ----
        if (kt < 31) { CP_WAIT(1); } else { CP_WAIT(0); }
        __syncthreads();

        // ---- O += P V : B = VT[d][k], 8 d-fragments. ----
#pragma unroll
        for (int bs = 0; bs < 2; bs++) {
#pragma unroll
            for (int j = 0; j < 8; j++) {
                uint32_t vh4[4], vl4[4];
                uint32_t bd = b_off + (uint32_t)(j * 8 * AT) * 2 + bs * 64;
                LDM_X4(vh4, uVh + bd);
                LDM_X4(vl4, uVl + bd);
                MMA_BF16(oacc[j], ph[2 * bs], (vh4 + 0));
                MMA_BF16(oacc[j], ph[2 * bs], (vl4 + 0));
                MMA_BF16(oacc[j], pl[2 * bs], (vh4 + 0));
                MMA_BF16(oacc[j], ph[2 * bs + 1], (vh4 + 2));
                MMA_BF16(oacc[j], ph[2 * bs + 1], (vl4 + 2));
                MMA_BF16(oacc[j], pl[2 * bs + 1], (vh4 + 2));
            }
        }

        if (kt < 31) {
            __syncthreads();   // all warps done reading Vbuf
            const int kn = (kt + 1) << 6;
#pragma unroll
            for (int j = 0; j < 4; j++) {
                int idx = tid + j * 128;
                int r = idx >> 3, c = (idx & 7) * 8;
                uint32_t so = (uint32_t)(r * AT + c) * 2;
                size_t gv = (size_t)r * SEQ + kn + c;
                cp16(uVh + so, &gVh[gv]);
                cp16(uVl + so, &gVl[gv]);
            }
            CP_COMMIT();
        }
    }

    // ---- Epilogue ----
#pragma unroll
    for (int off = 1; off < 4; off <<= 1) {
        lsum0 += __shfl_xor_sync(0xffffffffu, lsum0, off);
        lsum1 += __shfl_xor_sync(0xffffffffu, lsum1, off);
    }
    const float inv0 = 0.125f / lsum0;
    const float inv1 = 0.125f / lsum1;

    const int g = lane >> 2;
    const int t2 = (lane & 3) << 1;
    const int b = bh / NH;
    const int h = bh - b * NH;
    const int row0 = q0 + wq * 16 + g;
    float* base0 = out + ((size_t)(b * SEQ + row0)) * EMB + h * HD;
    float* base1 = base0 + (size_t)8 * EMB;
#pragma unroll
    for (int j = 0; j < 8; j++) {
        *(float2*)&base0[j * 8 + t2] = make_float2(oacc[j][0] * inv0, oacc[j][1] * inv0);
        *(float2*)&base1[j * 8 + t2] = make_float2(oacc[j][2] * inv1, oacc[j][3] * inv1);
    }
}

// ============================================================================
extern "C" void kernel_launch(void* const* d_in, const int* in_sizes, int n_in,
                              void* d_out, int out_size)
{
    const float* z = nullptr;
    const float* W = nullptr;
    const float* bias = nullptr;
    for (int i = 0; i < n_in; i++) {
        if (in_sizes[i] == NB * SEQ * EMB)      z = (const float*)d_in[i];
        else if (in_sizes[i] == EMB * NCOL)     W = (const float*)d_in[i];
        else if (in_sizes[i] == NCOL)           bias = (const float*)d_in[i];
    }
    float* out = (float*)d_out;

    convert_fused_kernel<<<ZB + WB, 256>>>(z, W);

    const int mma_smem = 2 * QSTG_B;   // 81920
    cudaFuncSetAttribute(qkv_mma_kernel, cudaFuncAttributeMaxDynamicSharedMemorySize,
                         mma_smem);
    qkv_mma_kernel<<<dim3(NCOL / 128, MROWS / 128), 256, mma_smem>>>(bias);

    const int attn_smem = 6 * ARR_B;   // 55296
    cudaFuncSetAttribute(attn_hmma_kernel, cudaFuncAttributeMaxDynamicSharedMemorySize,
                         attn_smem);
    attn_hmma_kernel<<<dim3(SEQ / 64, NB * NH), 128, attn_smem>>>(out);
}